// round 2
// baseline (speedup 1.0000x reference)
#include <cuda_runtime.h>

// SubPixelUpscaling r=2, NHWC: x [8,256,256,256] f32 -> out [8,512,512,64] f32
// out[n, 2h+r1, 2w+r2, c] = x[n, h, w, c*4 + r1*2 + r2]
//
// Per thread: one input pixel's channel-group g (16 input ch = 64 B = 4 float4
// loads, contiguous). Register 4x4 transpose -> 4 float4 stores, one per output
// sub-pixel, channels 4g..4g+3. All accesses 16B-vectorized, warp-coalesced.
//
// R2 changes vs R1 (dur 160.3 us, DRAM 81.6%):
//  - __launch_bounds__(256, 8): cap regs at 32 -> theoretical occupancy 64 warps
//    (was ~48 theoretical / 36 achieved), deeper DRAM queues.
//  - __ldcs/__stcs streaming hints: 1 GB pure stream, evict-first in L2.
//  - Output index = bit-field expansion of thread index (no multiplies).

static constexpr int G = 16;                       // float4 groups per out pixel
static constexpr long long NTHREADS = 8LL * 256 * 256 * G;  // 8,388,608

__global__ __launch_bounds__(256, 8)
void subpixel_upscale_kernel(const float4* __restrict__ in4,
                             float4* __restrict__ out4) {
    const unsigned idx = blockIdx.x * 256u + threadIdx.x;

    // idx bit layout: [22:20]=n [19:12]=h [11:4]=w [3:0]=g
    // out float4 index for sub-pixel (0,0):
    //   OB = n*(512*512*16) + (2h)*(512*16) + (2w)*16 + g
    //      = (n<<22) | (h<<14) | (w<<5) | g
    const unsigned OB = ((idx & 0x00700000u) << 2)    // n<<20 -> n<<22
                      | ((idx & 0x000FF000u) << 2)    // h<<12 -> h<<14
                      | ((idx & 0x00000FF0u) << 1)    // w<<4  -> w<<5
                      |  (idx & 0x0000000Fu);         // g

    const float4* p = in4 + (size_t)idx * 4;
    const float4 a0 = __ldcs(p + 0);   // c = 4g+0 ; comps = sub-pixels 0..3
    const float4 a1 = __ldcs(p + 1);   // c = 4g+1
    const float4 a2 = __ldcs(p + 2);   // c = 4g+2
    const float4 a3 = __ldcs(p + 3);   // c = 4g+3

    const unsigned ROW = 512 * G;      // 8192 float4s per output row

    __stcs(out4 + OB,           make_float4(a0.x, a1.x, a2.x, a3.x)); // (0,0)
    __stcs(out4 + OB + G,       make_float4(a0.y, a1.y, a2.y, a3.y)); // (0,1)
    __stcs(out4 + OB + ROW,     make_float4(a0.z, a1.z, a2.z, a3.z)); // (1,0)
    __stcs(out4 + OB + ROW + G, make_float4(a0.w, a1.w, a2.w, a3.w)); // (1,1)
}

extern "C" void kernel_launch(void* const* d_in, const int* in_sizes, int n_in,
                              void* d_out, int out_size) {
    const float4* in4 = (const float4*)d_in[0];
    float4* out4 = (float4*)d_out;

    const int threads = 256;
    const int blocks = (int)(NTHREADS / threads);   // 32768
    subpixel_upscale_kernel<<<blocks, threads>>>(in4, out4);
}